// round 6
// baseline (speedup 1.0000x reference)
#include <cuda_runtime.h>
#include <cstdio>
#include <cstdlib>

#define NB 16
#define LAT 16
#define HID 512
#define NNODES 262144
#define START 4097
#define NFC 16
#define NCOL 131104   // 2 * 16 * 4097

// ---------------- scratch (static device globals; no allocation) ----------------
__device__ float g_h1[HID * NB];                          // [512][16]
__device__ float g_fc2[2 * NFC * START * NB];             // [br][16][4097][16]
__device__ float g_t0[2 * 8 * 16385 * NB];                // [br][8][16385][16]
__device__ float g_t1[2 * 4 * 65537 * NB];                // [br][4][65537][16]
__device__ float g_t2[2 * NNODES * NB];                   // [br][262144][16]

__device__ int g_cls[9];
__device__ double g_stats[32];

struct P12 { const int* p[12]; int n; };

// ---------------- classify the nine 262144-element inputs by content ----------------
__global__ void k_classify(P12 ps) {
    if (threadIdx.x != 0 || blockIdx.x != 0) return;
    int type[12];   // 0 zero, 1 minus, 2 plus, 3 ord
    for (int a = 0; a < ps.n; a++) {
        const int* q = ps.p[a];
        int orv = 0;
        for (int k = 0; k < 32; k++) orv |= q[k];
        if (orv == 0)                       { type[a] = 0; continue; }
        if (q[0] == q[1])                   { type[a] = 1; continue; }
        if (q[NNODES - 2] == q[NNODES - 1]) { type[a] = 2; continue; }
        type[a] = 3;
    }
    int ords[2] = {0, 0}, no = 0;
    for (int a = 0; a < ps.n; a++) if (type[a] == 3 && no < 2) ords[no++] = a;
    for (int b = 0; b < 2; b++) {
        int o = ords[b];
        const int* oq = ps.p[o];
        int mi = o, pi = o;
        for (int a = 0; a < ps.n; a++) {
            if (type[a] == 1) {
                bool ok = true;
                for (int k = 0; k < 8; k++) if (ps.p[a][k + 1] != oq[k]) ok = false;
                if (ok) mi = a;
            } else if (type[a] == 2) {
                bool ok = true;
                for (int k = 0; k < 8; k++) if (ps.p[a][k] != oq[k + 1]) ok = false;
                if (ok) pi = a;
            }
        }
        g_cls[3 * b + 0] = o;
        g_cls[3 * b + 1] = mi;
        g_cls[3 * b + 2] = pi;
    }
    int nz = 0;
    for (int a = 0; a < ps.n; a++) if (type[a] == 0 && nz < 3) g_cls[6 + nz++] = a;
}

// ---------------- fc1 ----------------
__global__ void k_fc1(const float* __restrict__ x, const float* __restrict__ w,
                      const float* __restrict__ bias) {
    __shared__ float xs[NB * LAT];
    int t = threadIdx.x;                 // 0..511
    if (t < NB * LAT) xs[t] = x[t];
    __syncthreads();
    float acc[NB];
    float bv = bias[t];
#pragma unroll
    for (int b = 0; b < NB; b++) acc[b] = bv;
#pragma unroll
    for (int l = 0; l < LAT; l++) {
        float wv = w[l * HID + t];
#pragma unroll
        for (int b = 0; b < NB; b++) acc[b] += xs[b * LAT + l] * wv;
    }
#pragma unroll
    for (int b = 0; b < NB; b++) g_h1[t * NB + b] = tanhf(acc[b]);
}

// ---------------- fc2 ----------------
__global__ void k_fc2(const float* __restrict__ w, const float* __restrict__ bias) {
    __shared__ __align__(16) float hs[HID * NB];   // 32 KB
    int t = threadIdx.x;                           // 256
    for (int e = t; e < HID * NB / 4; e += 256)
        ((float4*)hs)[e] = ((const float4*)g_h1)[e];
    __syncthreads();
    int c = blockIdx.x * 256 + t;
    if (c >= NCOL) return;
    float bv = bias[c];
    float acc[NB];
#pragma unroll
    for (int b = 0; b < NB; b++) acc[b] = bv;
    const float* wp = w + c;
#pragma unroll 2
    for (int k = 0; k < HID; k++) {
        float wv = wp[(size_t)k * NCOL];
        const float4* hp = (const float4*)(hs + k * NB);
        float4 h0 = hp[0], h1 = hp[1], h2 = hp[2], h3 = hp[3];
        acc[0]  += h0.x * wv; acc[1]  += h0.y * wv; acc[2]  += h0.z * wv; acc[3]  += h0.w * wv;
        acc[4]  += h1.x * wv; acc[5]  += h1.y * wv; acc[6]  += h1.z * wv; acc[7]  += h1.w * wv;
        acc[8]  += h2.x * wv; acc[9]  += h2.y * wv; acc[10] += h2.z * wv; acc[11] += h2.w * wv;
        acc[12] += h3.x * wv; acc[13] += h3.y * wv; acc[14] += h3.z * wv; acc[15] += h3.w * wv;
    }
    int br = c & 1;
    int j  = c >> 1;
    int ch = j / START;
    int pos = j - ch * START;
    float* dst = g_fc2 + (size_t)(((br * NFC + ch) * START) + pos) * NB;
#pragma unroll
    for (int q = 0; q < 4; q++) {
        float4 o;
        o.x = tanhf(acc[4 * q + 0]); o.y = tanhf(acc[4 * q + 1]);
        o.z = tanhf(acc[4 * q + 2]); o.w = tanhf(acc[4 * q + 3]);
        ((float4*)dst)[q] = o;
    }
}

// ---------------- transposed conv ----------------
template <int Cin, int Cout, int Lin, int Lout>
__global__ void k_convt(const float* __restrict__ xb, float* __restrict__ yb,
                        const float* __restrict__ w0, const float* __restrict__ b0c,
                        const float* __restrict__ w1, const float* __restrict__ b1c) {
    const int TS = 23;  // input halo: u0-3 .. u0+19
    __shared__ __align__(16) float xs[Cin * TS * NB];
    __shared__ float ws[Cin * Cout * 32];
    __shared__ float bsm[Cout];

    int br = blockIdx.y;
    const float* x  = xb + (size_t)br * Cin * Lin * NB;
    float*       y  = yb + (size_t)br * Cout * Lout * NB;
    const float* w  = br ? w1 : w0;
    const float* bc = br ? b1c : b0c;

    int t = threadIdx.x;  // 256
    for (int e = t; e < Cin * Cout * 32; e += 256) ws[e] = w[e];
    if (t < Cout) bsm[t] = bc[t];

    int u0 = blockIdx.x * 16;
    for (int e = t; e < Cin * TS * NB; e += 256) {
        int ci  = e / (TS * NB);
        int rem = e - ci * TS * NB;
        int tl  = rem >> 4;
        int b   = rem & 15;
        int tg  = u0 - 3 + tl;
        float v = 0.0f;
        if (tg >= 0 && tg < Lin) v = x[((size_t)ci * Lin + tg) * NB + b];
        xs[e] = v;   // layout [ci][tl][b]
    }
    __syncthreads();

    int nl = t >> 2;     // 0..63 local output position
    int bq = t & 3;      // batch quad
    int du = nl >> 2;    // u - u0
    int r  = nl & 3;

    float acc[Cout][4];
#pragma unroll
    for (int co = 0; co < Cout; co++) {
        float bv = bsm[co];
        acc[co][0] = bv; acc[co][1] = bv; acc[co][2] = bv; acc[co][3] = bv;
    }

    for (int ci = 0; ci < Cin; ci++) {
#pragma unroll
        for (int q = 0; q < 8; q++) {
            int tl = du + 7 - q;
            float4 xv = *(const float4*)&xs[(ci * TS + tl) * NB + bq * 4];
#pragma unroll
            for (int co = 0; co < Cout; co++) {
                float wv = ws[(ci * Cout + co) * 32 + r + 4 * q];
                acc[co][0] += xv.x * wv; acc[co][1] += xv.y * wv;
                acc[co][2] += xv.z * wv; acc[co][3] += xv.w * wv;
            }
        }
    }

    int n = u0 * 4 + nl;
    if (n < Lout) {
#pragma unroll
        for (int co = 0; co < Cout; co++) {
            float4 o;
            o.x = tanhf(acc[co][0]); o.y = tanhf(acc[co][1]);
            o.z = tanhf(acc[co][2]); o.w = tanhf(acc[co][3]);
            *(float4*)&y[((size_t)co * Lout + n) * NB + bq * 4] = o;
        }
    }
}

// ---------------- gather + weighted sums + final combine ----------------
__global__ void k_final(P12 ps,
                        const float* __restrict__ sp0w, const float* __restrict__ sp1w,
                        const float* __restrict__ fw, float* __restrict__ out) {
    __shared__ int cls[9];
    if (threadIdx.x < 9) cls[threadIdx.x] = g_cls[threadIdx.x];
    __syncthreads();
    const int* ord0 = ps.p[cls[0]];
    const int* m0   = ps.p[cls[1]];
    const int* p0   = ps.p[cls[2]];
    const int* ord1 = ps.p[cls[3]];
    const int* m1   = ps.p[cls[4]];
    const int* p1   = ps.p[cls[5]];
    const float* sp0b = (const float*)ps.p[cls[6]];
    const float* sp1b = (const float*)ps.p[cls[7]];
    const float* fb   = (const float*)ps.p[cls[8]];

    int idx = blockIdx.x * 256 + threadIdx.x;    // 4 * NNODES threads
    int n  = idx & (NNODES - 1);
    int bq = idx >> 18;
    const float* t2a = g_t2;
    const float* t2b = g_t2 + (size_t)NNODES * NB;

    float4 a0 = *(const float4*)(t2a + (size_t)m0[n]   * NB + bq * 4);
    float4 c0 = *(const float4*)(t2a + (size_t)ord0[n] * NB + bq * 4);
    float4 d0 = *(const float4*)(t2a + (size_t)p0[n]   * NB + bq * 4);
    float wa0 = sp0w[3 * n], wb0 = sp0w[3 * n + 1], wc0 = sp0w[3 * n + 2], bb0 = sp0b[n];
    float4 v0;
    v0.x = tanhf(a0.x * wa0 + c0.x * wb0 + d0.x * wc0 + bb0);
    v0.y = tanhf(a0.y * wa0 + c0.y * wb0 + d0.y * wc0 + bb0);
    v0.z = tanhf(a0.z * wa0 + c0.z * wb0 + d0.z * wc0 + bb0);
    v0.w = tanhf(a0.w * wa0 + c0.w * wb0 + d0.w * wc0 + bb0);

    float4 a1 = *(const float4*)(t2b + (size_t)m1[n]   * NB + bq * 4);
    float4 c1 = *(const float4*)(t2b + (size_t)ord1[n] * NB + bq * 4);
    float4 d1 = *(const float4*)(t2b + (size_t)p1[n]   * NB + bq * 4);
    float wa1 = sp1w[3 * n], wb1 = sp1w[3 * n + 1], wc1 = sp1w[3 * n + 2], bb1 = sp1b[n];
    float4 v1;
    v1.x = tanhf(a1.x * wa1 + c1.x * wb1 + d1.x * wc1 + bb1);
    v1.y = tanhf(a1.y * wa1 + c1.y * wb1 + d1.y * wc1 + bb1);
    v1.z = tanhf(a1.z * wa1 + c1.z * wb1 + d1.z * wc1 + bb1);
    v1.w = tanhf(a1.w * wa1 + c1.w * wb1 + d1.w * wc1 + bb1);

    float fa = fw[2 * n], fbv = fw[2 * n + 1], fbb = fb[n];
    out[(size_t)(bq * 4 + 0) * NNODES + n] = tanhf(v0.x * fa + v1.x * fbv + fbb);
    out[(size_t)(bq * 4 + 1) * NNODES + n] = tanhf(v0.y * fa + v1.y * fbv + fbb);
    out[(size_t)(bq * 4 + 2) * NNODES + n] = tanhf(v0.z * fa + v1.z * fbv + fbb);
    out[(size_t)(bq * 4 + 3) * NNODES + n] = tanhf(v0.w * fa + v1.w * fbv + fbb);
}

// ---------------- diagnostics (non-capture path only) ----------------
__global__ void k_zstats() {
    if (blockIdx.x == 0 && threadIdx.x < 32) g_stats[threadIdx.x] = 0.0;
}

__global__ void k_stats(const float* __restrict__ out) {
    long long tid = blockIdx.x * (long long)blockDim.x + threadIdx.x;
    long long nt = gridDim.x * (long long)blockDim.x;
    double s;
#define SUMSQ(ptr, n, slot) \
    s = 0; for (long long i = tid; i < (long long)(n); i += nt) { double v = (double)(ptr)[i]; s += v * v; } \
    atomicAdd(&g_stats[slot], s);
    SUMSQ(g_h1, HID * NB, 0)
    SUMSQ(g_fc2, 2LL * NFC * START * NB, 1)
    SUMSQ(g_t0, 2LL * 8 * 16385 * NB, 2)
    SUMSQ(g_t1, 2LL * 4 * 65537 * NB, 3)
    SUMSQ(g_t2, 2LL * NNODES * NB, 4)
    SUMSQ(out, (long long)NB * NNODES, 5)
#undef SUMSQ
}

// ---------------- host ----------------
static void dump_and_die(const char* why, const int* in_sizes, int n_in, int out_size) {
    fprintf(stderr, "[kl-FATAL] %s\n[kl] n_in=%d out_size=%d\n[kl] sizes:", why, n_in, out_size);
    for (int i = 0; i < n_in; i++) fprintf(stderr, " [%d]=%d", i, in_sizes[i]);
    fprintf(stderr, "\n");
    fflush(stderr);
    abort();
}

static void check_launch(const char* stage, const int* in_sizes, int n_in, int out_size) {
    cudaError_t e = cudaGetLastError();
    if (e != cudaSuccess) {
        char buf[256];
        snprintf(buf, sizeof(buf), "launch failed at %s: %s", stage, cudaGetErrorString(e));
        dump_and_die(buf, in_sizes, n_in, out_size);
    }
}

extern "C" void kernel_launch(void* const* d_in, const int* in_sizes, int n_in,
                              void* d_out, int out_size) {
    const float *x = 0, *f1w = 0, *f1b = 0, *f2w = 0, *f2b = 0, *fspw = 0;
    const float *ctw[2][3] = {{0}}, *ctb[2][3] = {{0}}, *spw[2] = {0, 0};
    int nw0 = 0, nw1 = 0, nw2 = 0, nb0 = 0, nb1 = 0, nb2 = 0, nsp = 0;
    int bad = 0;
    P12 ps; ps.n = 0;

    for (int i = 0; i < n_in; i++) {
        long long s = in_sizes[i];
        const float* fp = (const float*)d_in[i];
        switch (s) {
            case 256:       x = fp; break;
            case 8192:      f1w = fp; break;
            case 512:       f1b = fp; break;
            case 67125248:  f2w = fp; break;
            case 131104:    f2b = fp; break;
            case 524288:    fspw = fp; break;
            case 4096:      if (nw0 < 2) ctw[nw0++][0] = fp; else bad = 1; break;
            case 1024:      if (nw1 < 2) ctw[nw1++][1] = fp; else bad = 1; break;
            case 128:       if (nw2 < 2) ctw[nw2++][2] = fp; else bad = 1; break;
            case 8:         if (nb0 < 2) ctb[nb0++][0] = fp; else bad = 1; break;
            case 4:         if (nb1 < 2) ctb[nb1++][1] = fp; else bad = 1; break;
            case 1:         if (nb2 < 2) ctb[nb2++][2] = fp; else bad = 1; break;
            case 786432:    if (nsp < 2) spw[nsp++] = fp; else bad = 1; break;
            case 262144:    if (ps.n < 12) ps.p[ps.n++] = (const int*)d_in[i]; else bad = 1; break;
            default: bad = 1; break;
        }
    }
    if (bad || n_in != 29 || !x || !f1w || !f1b || !f2w || !f2b || !fspw ||
        nw0 != 2 || nw1 != 2 || nw2 != 2 || nb0 != 2 || nb1 != 2 || nb2 != 2 ||
        nsp != 2 || ps.n != 9 || out_size != NB * NNODES) {
        dump_and_die("input-binding mismatch", in_sizes, n_in, out_size);
    }

    // RESOLVE DEVICE ADDRESSES of scratch symbols (the round-5 root cause:
    // passing a __device__ symbol as a kernel arg from host passes the host
    // shadow address; on GB300 ATS makes it dereferenceable -> silent zeros).
    float *fc2p = 0, *t0p = 0, *t1p = 0, *t2p = 0;
    cudaError_t ea = cudaGetSymbolAddress((void**)&fc2p, g_fc2);
    cudaError_t eb = cudaGetSymbolAddress((void**)&t0p,  g_t0);
    cudaError_t ec = cudaGetSymbolAddress((void**)&t1p,  g_t1);
    cudaError_t ed = cudaGetSymbolAddress((void**)&t2p,  g_t2);
    if (ea != cudaSuccess || eb != cudaSuccess || ec != cudaSuccess || ed != cudaSuccess)
        dump_and_die("cudaGetSymbolAddress failed", in_sizes, n_in, out_size);

    float* out = (float*)d_out;

    cudaStreamCaptureStatus cst = cudaStreamCaptureStatusNone;
    cudaError_t qe = cudaStreamIsCapturing(0, &cst);
    bool capturing = (qe != cudaSuccess) || (cst != cudaStreamCaptureStatusNone);
    (void)cudaGetLastError();

    k_classify<<<1, 32>>>(ps);
    check_launch("classify", in_sizes, n_in, out_size);
    k_fc1<<<1, 512>>>(x, f1w, f1b);
    check_launch("fc1", in_sizes, n_in, out_size);
    k_fc2<<<(NCOL + 255) / 256, 256>>>(f2w, f2b);
    check_launch("fc2", in_sizes, n_in, out_size);

    k_convt<16, 8, 4097, 16385><<<dim3(257, 2), 256>>>(fc2p, t0p, ctw[0][0], ctb[0][0], ctw[1][0], ctb[1][0]);
    check_launch("conv0", in_sizes, n_in, out_size);
    k_convt<8, 4, 16385, 65537><<<dim3(1025, 2), 256>>>(t0p, t1p, ctw[0][1], ctb[0][1], ctw[1][1], ctb[1][1]);
    check_launch("conv1", in_sizes, n_in, out_size);
    k_convt<4, 1, 65537, 262144><<<dim3(4096, 2), 256>>>(t1p, t2p, ctw[0][2], ctb[0][2], ctw[1][2], ctb[1][2]);
    check_launch("conv2", in_sizes, n_in, out_size);

    k_final<<<(4 * NNODES) / 256, 256>>>(ps, spw[0], spw[1], fspw, out);
    check_launch("final", in_sizes, n_in, out_size);

    if (!capturing) {
        k_zstats<<<1, 64>>>();
        k_stats<<<64, 256>>>(out);
        check_launch("stats", in_sizes, n_in, out_size);
        double st[32];
        if (cudaMemcpyFromSymbol(st, g_stats, sizeof(st)) == cudaSuccess) {
            fprintf(stderr,
                    "[diag] h1=%.4e fc2=%.4e t0=%.4e t1=%.4e t2=%.4e out2=%.4e\n",
                    st[0], st[1], st[2], st[3], st[4], st[5]);
            fflush(stderr);
            bool sick = false;
            for (int i = 0; i < 6; i++)
                if (!(st[i] > 0.0) || !(st[i] < 1e30) || st[i] != st[i]) sick = true;
            if (sick) dump_and_die("pipeline stage dead (see [diag])", in_sizes, n_in, out_size);
        }
    }
}

// round 7
// speedup vs baseline: 1.1438x; 1.1438x over previous
#include <cuda_runtime.h>
#include <cstdio>
#include <cstdlib>

typedef unsigned long long ull;

#define NB 16
#define LAT 16
#define HID 512
#define NNODES 262144
#define START 4097
#define NFC 16
#define NCOL 131104   // 2 * 16 * 4097

// ---------------- scratch (static device globals; no allocation) ----------------
__device__ float g_h1[HID * NB];                          // [512][16]
__device__ float g_fc2[2 * NFC * START * NB];             // [br][16][4097][16]
__device__ float g_t0[2 * 8 * 16385 * NB];                // [br][8][16385][16]
__device__ float g_t1[2 * 4 * 65537 * NB];                // [br][4][65537][16]
__device__ float g_t2[2 * NNODES * NB];                   // [br][262144][16]

__device__ int g_cls[9];

struct P12 { const int* p[12]; int n; };

// ---------------- helpers ----------------
static __device__ __forceinline__ ull pack2(float v) {
    ull r; asm("mov.b64 %0, {%1, %1};" : "=l"(r) : "f"(v)); return r;
}
static __device__ __forceinline__ ull ffma2(ull a, ull b, ull c) {
    ull d; asm("fma.rn.f32x2 %0, %1, %2, %3;" : "=l"(d) : "l"(a), "l"(b), "l"(c)); return d;
}
static __device__ __forceinline__ float2 unpack2(ull v) {
    float2 f; asm("mov.b64 {%0, %1}, %2;" : "=f"(f.x), "=f"(f.y) : "l"(v)); return f;
}
static __device__ __forceinline__ float tanh_fast(float x) {
    float ax = fabsf(x);
    float e  = __expf(-2.0f * ax);
    float r  = __fdividef(1.0f - e, 1.0f + e);
    return copysignf(r, x);
}

// ---------------- classify the nine 262144-element inputs (parallel) ----------------
__global__ void k_classify(P12 ps) {
    __shared__ int first[12][9];
    __shared__ int last2[12][2];
    __shared__ int type[12];
    int w = threadIdx.x >> 5, lane = threadIdx.x & 31;
    if (w < ps.n) {
        const int* q = ps.p[w];
        int v = q[lane];
        unsigned nzm = __ballot_sync(0xffffffffu, v != 0);
        if (lane < 9) first[w][lane] = q[lane];
        if (lane < 2) last2[w][lane] = q[NNODES - 2 + lane];
        if (lane == 0) {
            int ty;
            if (nzm == 0u) ty = 0;                        // zero bias
            else if (q[0] == q[1]) ty = 1;                // minus
            else if (q[NNODES - 2] == q[NNODES - 1]) ty = 2; // plus
            else ty = 3;                                  // ord
            type[w] = ty;
        }
    }
    __syncthreads();
    if (threadIdx.x == 0) {
        int ords[2] = {0, 0}, no = 0;
        for (int a = 0; a < ps.n; a++) if (type[a] == 3 && no < 2) ords[no++] = a;
        for (int b = 0; b < 2; b++) {
            int o = ords[b];
            int mi = o, pi = o;
            for (int a = 0; a < ps.n; a++) {
                if (type[a] == 1) {
                    bool ok = true;
                    for (int k = 0; k < 8; k++) if (first[a][k + 1] != first[o][k]) ok = false;
                    if (ok) mi = a;
                } else if (type[a] == 2) {
                    bool ok = true;
                    for (int k = 0; k < 8; k++) if (first[a][k] != first[o][k + 1]) ok = false;
                    if (ok) pi = a;
                }
            }
            g_cls[3 * b + 0] = o;
            g_cls[3 * b + 1] = mi;
            g_cls[3 * b + 2] = pi;
        }
        int nz = 0;
        for (int a = 0; a < ps.n; a++) if (type[a] == 0 && nz < 3) g_cls[6 + nz++] = a;
        (void)last2;
    }
}

// ---------------- fc1 ----------------
__global__ void k_fc1(const float* __restrict__ x, const float* __restrict__ w,
                      const float* __restrict__ bias) {
    __shared__ float xs[NB * LAT];
    int t = threadIdx.x;                 // 0..511
    if (t < NB * LAT) xs[t] = x[t];
    __syncthreads();
    float acc[NB];
    float bv = bias[t];
#pragma unroll
    for (int b = 0; b < NB; b++) acc[b] = bv;
#pragma unroll
    for (int l = 0; l < LAT; l++) {
        float wv = w[l * HID + t];
#pragma unroll
        for (int b = 0; b < NB; b++) acc[b] += xs[b * LAT + l] * wv;
    }
#pragma unroll
    for (int b = 0; b < NB; b++) g_h1[t * NB + b] = tanh_fast(acc[b]);
}

// ---------------- fc2: 2 adjacent columns per thread, f32x2 ----------------
__global__ void k_fc2(const float* __restrict__ w, const float* __restrict__ bias) {
    __shared__ __align__(16) ull hs2[HID * 8];      // [512][8] batch-pairs, 32 KB
    int t = threadIdx.x;                             // 128 threads
    {
        const float4* src = (const float4*)g_h1;
        float4* dst = (float4*)hs2;
        for (int e = t; e < HID * NB / 4; e += 128) dst[e] = src[e];
    }
    __syncthreads();
    int c0 = blockIdx.x * 256 + 2 * t;
    if (c0 >= NCOL) return;
    float2 bv = *(const float2*)(bias + c0);
    ull acc0[8], acc1[8];
#pragma unroll
    for (int j = 0; j < 8; j++) { acc0[j] = pack2(bv.x); acc1[j] = pack2(bv.y); }
#pragma unroll 8
    for (int k = 0; k < HID; k++) {
        float2 wv = *(const float2*)(w + (size_t)k * NCOL + c0);
        ull w0 = pack2(wv.x), w1 = pack2(wv.y);
        const ull* hp = hs2 + k * 8;
#pragma unroll
        for (int j = 0; j < 8; j++) {
            ull hv = hp[j];
            acc0[j] = ffma2(w0, hv, acc0[j]);
            acc1[j] = ffma2(w1, hv, acc1[j]);
        }
    }
    // c0 even -> branch 0 ; c0+1 -> branch 1 ; same (ch,pos)
    int j  = c0 >> 1;
    int ch = j / START;
    int pos = j - ch * START;
    float* dst0 = g_fc2 + (size_t)(ch * START + pos) * NB;
    float* dst1 = dst0 + (size_t)NFC * START * NB;
#pragma unroll
    for (int q = 0; q < 4; q++) {
        float2 a = unpack2(acc0[2 * q]), b = unpack2(acc0[2 * q + 1]);
        float4 o; o.x = tanh_fast(a.x); o.y = tanh_fast(a.y);
        o.z = tanh_fast(b.x); o.w = tanh_fast(b.y);
        ((float4*)dst0)[q] = o;
    }
#pragma unroll
    for (int q = 0; q < 4; q++) {
        float2 a = unpack2(acc1[2 * q]), b = unpack2(acc1[2 * q + 1]);
        float4 o; o.x = tanh_fast(a.x); o.y = tanh_fast(a.y);
        o.z = tanh_fast(b.x); o.w = tanh_fast(b.y);
        ((float4*)dst1)[q] = o;
    }
}

// ---------------- transposed conv, f32x2 + dup-weight smem ----------------
// thread map (256 thr): ww = t>>5 (8 warps); r = ww&3 (warp-uniform phase);
// uhalf = ww>>2; lane: ul = lane>>2 (0..7), bq = lane&3. u = uhalf*8+ul (16 u/block).
template <int Cin, int Cout, int Lin, int Lout>
__global__ void k_convt(const float* __restrict__ xb, float* __restrict__ yb,
                        const float* __restrict__ w0, const float* __restrict__ b0c,
                        const float* __restrict__ w1, const float* __restrict__ b1c) {
    const int TS = 23;  // input halo: u0-3 .. u0+19
    __shared__ __align__(16) float xs[Cin * TS * NB];
    __shared__ __align__(16) ull ws2[Cin * Cout * 32];   // [(ci*8+q)*4+r][co], duplicated

    int br = blockIdx.y;
    const float* x  = xb + (size_t)br * Cin * Lin * NB;
    float*       y  = yb + (size_t)br * Cout * Lout * NB;
    const float* w  = br ? w1 : w0;
    const float* bc = br ? b1c : b0c;

    int t = threadIdx.x;  // 256
    for (int e = t; e < Cin * Cout * 32; e += 256) {
        int ci  = e / (Cout * 32);
        int rem = e - ci * (Cout * 32);
        int co  = rem >> 5;
        int k   = rem & 31;
        int q   = k >> 2, r = k & 3;
        ws2[((ci * 8 + q) * 4 + r) * Cout + co] = pack2(w[e]);
    }

    int u0 = blockIdx.x * 16;
    for (int e = t; e < Cin * TS * NB; e += 256) {
        int ci  = e / (TS * NB);
        int rem = e - ci * TS * NB;
        int tl  = rem >> 4;
        int b   = rem & 15;
        int tg  = u0 - 3 + tl;
        float v = 0.0f;
        if (tg >= 0 && tg < Lin) v = x[((size_t)ci * Lin + tg) * NB + b];
        xs[e] = v;   // layout [ci][tl][16b]
    }
    __syncthreads();

    int ww = t >> 5, lane = t & 31;
    int r  = ww & 3, uhalf = ww >> 2;
    int ul = lane >> 2, bq = lane & 3;
    int u  = uhalf * 8 + ul;

    ull acc[Cout][2];
#pragma unroll
    for (int co = 0; co < Cout; co++) {
        ull bv = pack2(bc[co]);
        acc[co][0] = bv; acc[co][1] = bv;
    }

    for (int ci = 0; ci < Cin; ci++) {
#pragma unroll
        for (int q = 0; q < 8; q++) {
            int tl = u + 7 - q;
            ulonglong2 xv = *(const ulonglong2*)&xs[(ci * TS + tl) * NB + bq * 4];
            const ull* wp = ws2 + ((ci * 8 + q) * 4 + r) * Cout;
#pragma unroll
            for (int co = 0; co < Cout; co++) {
                ull wd = wp[co];                       // warp-uniform broadcast
                acc[co][0] = ffma2(wd, xv.x, acc[co][0]);
                acc[co][1] = ffma2(wd, xv.y, acc[co][1]);
            }
        }
    }

    int n = (u0 + u) * 4 + r;
    if (n < Lout) {
#pragma unroll
        for (int co = 0; co < Cout; co++) {
            float2 a = unpack2(acc[co][0]), b = unpack2(acc[co][1]);
            float4 o;
            o.x = tanh_fast(a.x); o.y = tanh_fast(a.y);
            o.z = tanh_fast(b.x); o.w = tanh_fast(b.y);
            *(float4*)&y[((size_t)co * Lout + n) * NB + bq * 4] = o;
        }
    }
}

// ---------------- gather + weighted sums + final combine ----------------
__global__ void k_final(P12 ps,
                        const float* __restrict__ sp0w, const float* __restrict__ sp1w,
                        const float* __restrict__ fw, float* __restrict__ out) {
    __shared__ int cls[9];
    if (threadIdx.x < 9) cls[threadIdx.x] = g_cls[threadIdx.x];
    __syncthreads();
    const int* ord0 = ps.p[cls[0]];
    const int* m0   = ps.p[cls[1]];
    const int* p0   = ps.p[cls[2]];
    const int* ord1 = ps.p[cls[3]];
    const int* m1   = ps.p[cls[4]];
    const int* p1   = ps.p[cls[5]];
    const float* sp0b = (const float*)ps.p[cls[6]];
    const float* sp1b = (const float*)ps.p[cls[7]];
    const float* fb   = (const float*)ps.p[cls[8]];

    int idx = blockIdx.x * 256 + threadIdx.x;    // 4 * NNODES threads
    int n  = idx & (NNODES - 1);
    int bq = idx >> 18;
    const float* t2a = g_t2;
    const float* t2b = g_t2 + (size_t)NNODES * NB;

    float4 a0 = *(const float4*)(t2a + (size_t)m0[n]   * NB + bq * 4);
    float4 c0 = *(const float4*)(t2a + (size_t)ord0[n] * NB + bq * 4);
    float4 d0 = *(const float4*)(t2a + (size_t)p0[n]   * NB + bq * 4);
    float wa0 = sp0w[3 * n], wb0 = sp0w[3 * n + 1], wc0 = sp0w[3 * n + 2], bb0 = sp0b[n];
    float4 v0;
    v0.x = tanh_fast(a0.x * wa0 + c0.x * wb0 + d0.x * wc0 + bb0);
    v0.y = tanh_fast(a0.y * wa0 + c0.y * wb0 + d0.y * wc0 + bb0);
    v0.z = tanh_fast(a0.z * wa0 + c0.z * wb0 + d0.z * wc0 + bb0);
    v0.w = tanh_fast(a0.w * wa0 + c0.w * wb0 + d0.w * wc0 + bb0);

    float4 a1 = *(const float4*)(t2b + (size_t)m1[n]   * NB + bq * 4);
    float4 c1 = *(const float4*)(t2b + (size_t)ord1[n] * NB + bq * 4);
    float4 d1 = *(const float4*)(t2b + (size_t)p1[n]   * NB + bq * 4);
    float wa1 = sp1w[3 * n], wb1 = sp1w[3 * n + 1], wc1 = sp1w[3 * n + 2], bb1 = sp1b[n];
    float4 v1;
    v1.x = tanh_fast(a1.x * wa1 + c1.x * wb1 + d1.x * wc1 + bb1);
    v1.y = tanh_fast(a1.y * wa1 + c1.y * wb1 + d1.y * wc1 + bb1);
    v1.z = tanh_fast(a1.z * wa1 + c1.z * wb1 + d1.z * wc1 + bb1);
    v1.w = tanh_fast(a1.w * wa1 + c1.w * wb1 + d1.w * wc1 + bb1);

    float fa = fw[2 * n], fbv = fw[2 * n + 1], fbb = fb[n];
    out[(size_t)(bq * 4 + 0) * NNODES + n] = tanh_fast(v0.x * fa + v1.x * fbv + fbb);
    out[(size_t)(bq * 4 + 1) * NNODES + n] = tanh_fast(v0.y * fa + v1.y * fbv + fbb);
    out[(size_t)(bq * 4 + 2) * NNODES + n] = tanh_fast(v0.z * fa + v1.z * fbv + fbb);
    out[(size_t)(bq * 4 + 3) * NNODES + n] = tanh_fast(v0.w * fa + v1.w * fbv + fbb);
}

// ---------------- host ----------------
static void dump_and_die(const char* why, const int* in_sizes, int n_in, int out_size) {
    fprintf(stderr, "[kl-FATAL] %s\n[kl] n_in=%d out_size=%d\n[kl] sizes:", why, n_in, out_size);
    for (int i = 0; i < n_in; i++) fprintf(stderr, " [%d]=%d", i, in_sizes[i]);
    fprintf(stderr, "\n");
    fflush(stderr);
    abort();
}

static void check_launch(const char* stage, const int* in_sizes, int n_in, int out_size) {
    cudaError_t e = cudaGetLastError();
    if (e != cudaSuccess) {
        char buf[256];
        snprintf(buf, sizeof(buf), "launch failed at %s: %s", stage, cudaGetErrorString(e));
        dump_and_die(buf, in_sizes, n_in, out_size);
    }
}

extern "C" void kernel_launch(void* const* d_in, const int* in_sizes, int n_in,
                              void* d_out, int out_size) {
    const float *x = 0, *f1w = 0, *f1b = 0, *f2w = 0, *f2b = 0, *fspw = 0;
    const float *ctw[2][3] = {{0}}, *ctb[2][3] = {{0}}, *spw[2] = {0, 0};
    int nw0 = 0, nw1 = 0, nw2 = 0, nb0 = 0, nb1 = 0, nb2 = 0, nsp = 0;
    int bad = 0;
    P12 ps; ps.n = 0;

    for (int i = 0; i < n_in; i++) {
        long long s = in_sizes[i];
        const float* fp = (const float*)d_in[i];
        switch (s) {
            case 256:       x = fp; break;
            case 8192:      f1w = fp; break;
            case 512:       f1b = fp; break;
            case 67125248:  f2w = fp; break;
            case 131104:    f2b = fp; break;
            case 524288:    fspw = fp; break;
            case 4096:      if (nw0 < 2) ctw[nw0++][0] = fp; else bad = 1; break;
            case 1024:      if (nw1 < 2) ctw[nw1++][1] = fp; else bad = 1; break;
            case 128:       if (nw2 < 2) ctw[nw2++][2] = fp; else bad = 1; break;
            case 8:         if (nb0 < 2) ctb[nb0++][0] = fp; else bad = 1; break;
            case 4:         if (nb1 < 2) ctb[nb1++][1] = fp; else bad = 1; break;
            case 1:         if (nb2 < 2) ctb[nb2++][2] = fp; else bad = 1; break;
            case 786432:    if (nsp < 2) spw[nsp++] = fp; else bad = 1; break;
            case 262144:    if (ps.n < 12) ps.p[ps.n++] = (const int*)d_in[i]; else bad = 1; break;
            default: bad = 1; break;
        }
    }
    if (bad || n_in != 29 || !x || !f1w || !f1b || !f2w || !f2b || !fspw ||
        nw0 != 2 || nw1 != 2 || nw2 != 2 || nb0 != 2 || nb1 != 2 || nb2 != 2 ||
        nsp != 2 || ps.n != 9 || out_size != NB * NNODES) {
        dump_and_die("input-binding mismatch", in_sizes, n_in, out_size);
    }

    // Resolve DEVICE addresses of scratch symbols (host shadow addr is the trap).
    float *fc2p = 0, *t0p = 0, *t1p = 0, *t2p = 0;
    cudaError_t ea = cudaGetSymbolAddress((void**)&fc2p, g_fc2);
    cudaError_t eb = cudaGetSymbolAddress((void**)&t0p,  g_t0);
    cudaError_t ec = cudaGetSymbolAddress((void**)&t1p,  g_t1);
    cudaError_t ed = cudaGetSymbolAddress((void**)&t2p,  g_t2);
    if (ea != cudaSuccess || eb != cudaSuccess || ec != cudaSuccess || ed != cudaSuccess)
        dump_and_die("cudaGetSymbolAddress failed", in_sizes, n_in, out_size);

    float* out = (float*)d_out;

    k_classify<<<1, 384>>>(ps);
    check_launch("classify", in_sizes, n_in, out_size);
    k_fc1<<<1, 512>>>(x, f1w, f1b);
    check_launch("fc1", in_sizes, n_in, out_size);
    k_fc2<<<(NCOL + 255) / 256, 128>>>(f2w, f2b);
    check_launch("fc2", in_sizes, n_in, out_size);

    k_convt<16, 8, 4097, 16385><<<dim3(257, 2), 256>>>(fc2p, t0p, ctw[0][0], ctb[0][0], ctw[1][0], ctb[1][0]);
    check_launch("conv0", in_sizes, n_in, out_size);
    k_convt<8, 4, 16385, 65537><<<dim3(1025, 2), 256>>>(t0p, t1p, ctw[0][1], ctb[0][1], ctw[1][1], ctb[1][1]);
    check_launch("conv1", in_sizes, n_in, out_size);
    k_convt<4, 1, 65537, 262144><<<dim3(4096, 2), 256>>>(t1p, t2p, ctw[0][2], ctb[0][2], ctw[1][2], ctb[1][2]);
    check_launch("conv2", in_sizes, n_in, out_size);

    k_final<<<(4 * NNODES) / 256, 256>>>(ps, spw[0], spw[1], fspw, out);
    check_launch("final", in_sizes, n_in, out_size);
}